// round 12
// baseline (speedup 1.0000x reference)
#include <cuda_runtime.h>
#include <cuda_bf16.h>
#include <cuda_fp16.h>
#include <math.h>
#include <stdint.h>

#define T_TOK 8192
#define DM    2048
#define NH    16
#define DHEAD 128
#define SEQ   1024
#define NSEQ  8
#define GK    2048
#define QSCALE 0.08838834764831845f

// ---------------- scratch (static __device__, allocation-free) ----------------
__device__ float g_cos[SEQ * 64];
__device__ float g_sin[SEQ * 64];
__device__ __half g_hi[(size_t)T_TOK * DM];      // x-hi, later attention-out-hi
__device__ __half g_lo[(size_t)T_TOK * DM];      // x-lo, later attention-out-lo
__device__ __half g_qhl[(size_t)2 * T_TOK * DM]; // qhi | qlo
__device__ __half g_wh[(size_t)3 * DM * DM];     // fp16 weights (Wq|Wk|Wv or Wo)
__device__ __half g_khi[(size_t)T_TOK * DM];
__device__ __half g_klo[(size_t)T_TOK * DM];
__device__ __half g_vh[(size_t)T_TOK * DM];

// ---------------- helpers ----------------
__device__ __forceinline__ uint32_t smem_u32(const void* p) {
    uint32_t a;
    asm("{ .reg .u64 t; cvta.to.shared.u64 t, %1; cvt.u32.u64 %0, t; }" : "=r"(a) : "l"(p));
    return a;
}
template<int N> __device__ __forceinline__ void cp_wait() {
    asm volatile("cp.async.wait_group %0;" :: "n"(N) : "memory");
}
__device__ __forceinline__ void cp_commit() {
    asm volatile("cp.async.commit_group;" ::: "memory");
}
__device__ __forceinline__ void cp_async16(uint32_t saddr, const void* gaddr) {
    asm volatile("cp.async.cg.shared.global [%0], [%1], 16;" :: "r"(saddr), "l"(gaddr));
}
#define LDSM4(r0, r1, r2, r3, addr) \
    asm volatile("ldmatrix.sync.aligned.m8n8.x4.shared.b16 {%0,%1,%2,%3}, [%4];" \
        : "=r"(r0), "=r"(r1), "=r"(r2), "=r"(r3) : "r"(addr))
#define LDSM4T(r0, r1, r2, r3, addr) \
    asm volatile("ldmatrix.sync.aligned.m8n8.x4.trans.shared.b16 {%0,%1,%2,%3}, [%4];" \
        : "=r"(r0), "=r"(r1), "=r"(r2), "=r"(r3) : "r"(addr))
#define MMA16816F(d, a, b) \
    asm volatile("mma.sync.aligned.m16n8k16.row.col.f32.f16.f16.f32 " \
        "{%0,%1,%2,%3}, {%4,%5,%6,%7}, {%8,%9}, {%0,%1,%2,%3};" \
        : "+f"((d)[0]), "+f"((d)[1]), "+f"((d)[2]), "+f"((d)[3]) \
        : "r"((a)[0]), "r"((a)[1]), "r"((a)[2]), "r"((a)[3]), "r"((b)[0]), "r"((b)[1]))

__device__ __forceinline__ uint32_t pack_h2(float a, float b) {
    __half2 h = __floats2half2_rn(a, b);
    return *reinterpret_cast<uint32_t*>(&h);
}

// ---------------- fp16 hi/lo split ----------------
__global__ __launch_bounds__(256) void split_fp16_kernel(
    const float* __restrict__ in, __half* __restrict__ hi,
    __half* __restrict__ lo, int n4)
{
    int i = blockIdx.x * blockDim.x + threadIdx.x;
    if (i >= n4) return;
    float4 v = ((const float4*)in)[i];
    __half h0 = __float2half_rn(v.x), h1 = __float2half_rn(v.y);
    __half h2 = __float2half_rn(v.z), h3 = __float2half_rn(v.w);
    __half l0 = __float2half_rn(v.x - __half2float(h0));
    __half l1 = __float2half_rn(v.y - __half2float(h1));
    __half l2 = __float2half_rn(v.z - __half2float(h2));
    __half l3 = __float2half_rn(v.w - __half2float(h3));
    ((__half2*)hi)[2*i]   = __half2(h0, h1);
    ((__half2*)hi)[2*i+1] = __half2(h2, h3);
    ((__half2*)lo)[2*i]   = __half2(l0, l1);
    ((__half2*)lo)[2*i+1] = __half2(l2, l3);
}

// ---------------- fp16 plain convert ----------------
__global__ __launch_bounds__(256) void conv_fp16_kernel(
    const float* __restrict__ in, __half* __restrict__ out, int n4)
{
    int i = blockIdx.x * blockDim.x + threadIdx.x;
    if (i >= n4) return;
    float4 v = ((const float4*)in)[i];
    ((__half2*)out)[2*i]   = __floats2half2_rn(v.x, v.y);
    ((__half2*)out)[2*i+1] = __floats2half2_rn(v.z, v.w);
}

// ---------------- RoPE cos/sin table ----------------
__global__ void rope_table_kernel() {
    int i = blockIdx.x * blockDim.x + threadIdx.x;
    int pos = i >> 6, j = i & 63;
    float inv = exp2f(-(float)j * 0.2076205059304593f);
    float ang = (float)pos * inv;
    float s, c;
    sincosf(ang, &s, &c);
    g_cos[i] = c;
    g_sin[i] = s;
}

// ------- HMMA fp16x2 GEMM + fused rope/scatter/split epilogue (QKV mode) -------
#define BK 64
#define NCHUNK (GK / BK)
#define TILE_B 16384
#define STAGE_B (3 * TILE_B)      // Ahi | Alo | B = 49152
#define GEMM_SMEM (3 * STAGE_B)   // 147456

__global__ __launch_bounds__(256, 1) void gemm_fp16x2(
    const __half* __restrict__ Ahi, const __half* __restrict__ Alo,
    const __half* __restrict__ B,
    float* __restrict__ C0,                       // plain mode output
    __half* __restrict__ qhi, __half* __restrict__ qlo,
    __half* __restrict__ khi, __half* __restrict__ klo,
    __half* __restrict__ vh, float* __restrict__ cache,
    const int* __restrict__ btab, int qkv_mode)
{
    extern __shared__ __align__(1024) char smraw[];
    const uint32_t smb = smem_u32(smraw);
    const int tid = threadIdx.x;
    const int lane = tid & 31, wid = tid >> 5;
    const int wm = wid >> 2, wn = wid & 3;            // warp grid 2(M) x 4(N)
    const int bx = blockIdx.x;
    const int brow = bx * 128;                        // row into weight buffer
    const int bm = blockIdx.y * 128;

    const __half* srcs[3] = { Ahi + (size_t)bm * GK, Alo + (size_t)bm * GK,
                              B + (size_t)brow * GK };

    float acc[4][4][4];
    #pragma unroll
    for (int mt = 0; mt < 4; mt++)
        #pragma unroll
        for (int nt = 0; nt < 4; nt++)
            #pragma unroll
            for (int j = 0; j < 4; j++) acc[mt][nt][j] = 0.f;

    auto prefetch = [&](int chunk_idx, int stg) {
        const uint32_t stb = smb + stg * STAGE_B;
        const int k0 = chunk_idx * BK;
        #pragma unroll
        for (int tile = 0; tile < 3; tile++) {
            const __half* g = srcs[tile] + k0;
            const uint32_t sbase = stb + tile * TILE_B;
            #pragma unroll
            for (int i = 0; i < 4; i++) {
                int idx = tid + 256 * i;
                int r = idx >> 3, c = idx & 7;
                uint32_t so = sbase + r * 128 + ((c ^ (r & 7)) << 4);
                cp_async16(so, g + (size_t)r * GK + c * 8);
            }
        }
    };

    prefetch(0, 0); cp_commit();
    prefetch(1, 1); cp_commit();

    int cstage = 0, pstage = 2;
    for (int i = 0; i < NCHUNK; i++) {
        if (i + 1 < NCHUNK) cp_wait<1>(); else cp_wait<0>();
        __syncthreads();
        if (i + 2 < NCHUNK) { prefetch(i + 2, pstage); cp_commit(); }

        const uint32_t stb = smb + cstage * STAGE_B;
        #pragma unroll
        for (int ks = 0; ks < 4; ks++) {
            uint32_t af[2][4][4];
            uint32_t bf[4][2];
            #pragma unroll
            for (int mt = 0; mt < 4; mt++) {
                int row = wm * 64 + mt * 16 + (lane & 15);
                uint32_t ad = stb + row * 128 + ((((ks << 1) | (lane >> 4)) ^ (row & 7)) << 4);
                LDSM4(af[0][mt][0], af[0][mt][1], af[0][mt][2], af[0][mt][3], ad);
                LDSM4(af[1][mt][0], af[1][mt][1], af[1][mt][2], af[1][mt][3], ad + TILE_B);
            }
            #pragma unroll
            for (int nt2 = 0; nt2 < 2; nt2++) {
                int n = wn * 32 + nt2 * 16 + ((lane >> 4) << 3) + (lane & 7);
                uint32_t bd = stb + 2 * TILE_B + n * 128
                            + ((((ks << 1) | ((lane >> 3) & 1)) ^ (n & 7)) << 4);
                LDSM4(bf[nt2*2][0], bf[nt2*2][1], bf[nt2*2+1][0], bf[nt2*2+1][1], bd);
            }
            #pragma unroll
            for (int mt = 0; mt < 4; mt++)
                #pragma unroll
                for (int nt = 0; nt < 4; nt++)
                    MMA16816F(acc[mt][nt], af[0][mt], bf[nt]);   // hi*B
            #pragma unroll
            for (int mt = 0; mt < 4; mt++)
                #pragma unroll
                for (int nt = 0; nt < 4; nt++)
                    MMA16816F(acc[mt][nt], af[1][mt], bf[nt]);   // lo*B
        }
        cstage = (cstage == 2) ? 0 : cstage + 1;
        pstage = (pstage == 2) ? 0 : pstage + 1;
    }

    if (!qkv_mode) {
        // plain epilogue: fp32 store to C0
        const int col = (bx & 15) * 128;
        #pragma unroll
        for (int mt = 0; mt < 4; mt++) {
            int r0 = bm + wm * 64 + mt * 16 + (lane >> 2);
            #pragma unroll
            for (int nt = 0; nt < 4; nt++) {
                int c0 = col + wn * 32 + nt * 8 + ((lane & 3) << 1);
                float* cp = C0 + (size_t)r0 * DM + c0;
                *(float2*)cp = make_float2(acc[mt][nt][0], acc[mt][nt][1]);
                *(float2*)(cp + (size_t)8 * DM) = make_float2(acc[mt][nt][2], acc[mt][nt][3]);
            }
        }
        return;
    }

    // ---- fused QKV epilogue: stage -> rope/convert -> scatter/split ----
    __syncthreads();   // all stage-buffer readers done; reuse smem
    float* stile = (float*)smraw;   // [128][132]
    #pragma unroll
    for (int mt = 0; mt < 4; mt++) {
        int r0 = wm * 64 + mt * 16 + (lane >> 2);
        #pragma unroll
        for (int nt = 0; nt < 4; nt++) {
            int c0 = wn * 32 + nt * 8 + ((lane & 3) << 1);
            *(float2*)&stile[r0 * 132 + c0]       = make_float2(acc[mt][nt][0], acc[mt][nt][1]);
            *(float2*)&stile[(r0 + 8) * 132 + c0] = make_float2(acc[mt][nt][2], acc[mt][nt][3]);
        }
    }
    __syncthreads();

    const int kind = bx >> 4;      // 0=q, 1=k, 2=v
    const int h = bx & 15;
    if (kind < 2) {
        #pragma unroll 4
        for (int it = 0; it < 32; it++) {
            int idx = tid + 256 * it;       // 8192 (token, j) pairs
            int t = idx >> 6, j = idx & 63;
            int tok = bm + t;
            int pos = tok & (SEQ - 1);
            float c = g_cos[pos * 64 + j];
            float s = g_sin[pos * 64 + j];
            float a  = stile[t * 132 + j];
            float b2 = stile[t * 132 + j + 64];
            float r0 = a * c - b2 * s;
            float r1 = b2 * c + a * s;
            size_t gbase = (size_t)tok * DM + h * DHEAD + j;
            if (kind == 0) {
                r0 *= QSCALE; r1 *= QSCALE;
                __half h0 = __float2half_rn(r0), h1 = __float2half_rn(r1);
                qhi[gbase]      = h0;
                qhi[gbase + 64] = h1;
                qlo[gbase]      = __float2half_rn(r0 - __half2float(h0));
                qlo[gbase + 64] = __float2half_rn(r1 - __half2float(h1));
            } else {
                __half h0 = __float2half_rn(r0), h1 = __float2half_rn(r1);
                khi[gbase]      = h0;
                khi[gbase + 64] = h1;
                klo[gbase]      = __float2half_rn(r0 - __half2float(h0));
                klo[gbase + 64] = __float2half_rn(r1 - __half2float(h1));
                int seqi = tok >> 10, off = pos & 255;
                int phys = btab[seqi * 4 + (pos >> 8)];
                size_t cb = ((size_t)(phys * 32 + h) * 256 + off) * 128 + j;
                cache[cb]      = r0;
                cache[cb + 64] = r1;
            }
        }
    } else {
        #pragma unroll 4
        for (int it = 0; it < 64; it++) {
            int idx = tid + 256 * it;       // 16384 elements
            int t = idx >> 7, d = idx & 127;
            int tok = bm + t;
            int pos = tok & (SEQ - 1);
            float vv = stile[t * 132 + d];
            vh[(size_t)tok * DM + h * DHEAD + d] = __float2half_rn(vv);
            int seqi = tok >> 10, off = pos & 255;
            int phys = btab[seqi * 4 + (pos >> 8)];
            cache[((size_t)(phys * 32 + 16 + h) * 256 + off) * 128 + d] = vv;
        }
    }
}

// ---------------- flash attention, HMMA fp16, 3-stage pipeline ----------------
// Q: 64KB at smb; stages at smb+65536 + st*49152: Kh 16K | Kl 16K | V 16K
#define FAH_SMEM 212992

__global__ __launch_bounds__(256, 1) void flash_attn_hmma(
    const __half* __restrict__ Qhg, const __half* __restrict__ Qlg,
    const __half* __restrict__ Khg, const __half* __restrict__ Klg,
    const __half* __restrict__ Vhg,
    __half* __restrict__ Ohi, __half* __restrict__ Olo)
{
    extern __shared__ __align__(1024) char sm[];
    const uint32_t smb = smem_u32(sm);
    const uint32_t sQh = smb, sQl = smb + 32768;
    const int tid = threadIdx.x, lane = tid & 31, wq = tid >> 5;
    const int qt = (int)(gridDim.x - 1 - blockIdx.x);   // heavy tiles first
    const int h = blockIdx.y, b = blockIdx.z;
    const int tokQ = b * SEQ + qt * 128;
    const int nkt = 2 * qt + 2;

    auto load_kv = [&](int kt, int stg) {
        uint32_t st = smb + 65536 + stg * 49152;
        const __half* gh = Khg + (size_t)(b * SEQ + kt * 64) * DM + h * DHEAD;
        const __half* gl = Klg + (size_t)(b * SEQ + kt * 64) * DM + h * DHEAD;
        const __half* gv = Vhg + (size_t)(b * SEQ + kt * 64) * DM + h * DHEAD;
        #pragma unroll
        for (int i = 0; i < 4; i++) {
            int idx = tid + 256 * i;
            int r = idx >> 4, c = idx & 15;
            uint32_t off = r * 256 + ((c ^ (r & 7)) << 4);
            cp_async16(st + off, gh + (size_t)r * DM + c * 8);
            cp_async16(st + 16384 + off, gl + (size_t)r * DM + c * 8);
            cp_async16(st + 32768 + off, gv + (size_t)r * DM + c * 8);
        }
    };

    {
        const __half* gq = Qhg + (size_t)tokQ * DM + h * DHEAD;
        const __half* gl = Qlg + (size_t)tokQ * DM + h * DHEAD;
        #pragma unroll
        for (int i = 0; i < 8; i++) {
            int idx = tid + 256 * i;
            int r = idx >> 4, c = idx & 15;
            uint32_t off = r * 256 + ((c ^ (r & 7)) << 4);
            cp_async16(sQh + off, gq + (size_t)r * DM + c * 8);
            cp_async16(sQl + off, gl + (size_t)r * DM + c * 8);
        }
    }
    load_kv(0, 0); cp_commit();
    load_kv(1, 1); cp_commit();

    float m0 = -1e30f, m1 = -1e30f, l0 = 0.f, l1 = 0.f;
    float out[16][4];
    #pragma unroll
    for (int t = 0; t < 16; t++)
        #pragma unroll
        for (int j = 0; j < 4; j++) out[t][j] = 0.f;

    int cstage = 0, pstage = 2;
    for (int kt = 0; kt < nkt; kt++) {
        if (kt + 1 < nkt) cp_wait<1>(); else cp_wait<0>();
        __syncthreads();
        if (kt + 2 < nkt) { load_kv(kt + 2, pstage); cp_commit(); }

        const uint32_t sK = smb + 65536 + cstage * 49152;
        const uint32_t sV = sK + 32768;

        // ---- S = Q K^T (fp16 3-term, term-major) ----
        float sc[8][4];
        #pragma unroll
        for (int t = 0; t < 8; t++)
            #pragma unroll
            for (int j = 0; j < 4; j++) sc[t][j] = 0.f;

        #pragma unroll
        for (int ks = 0; ks < 8; ks++) {
            uint32_t ah[4], al[4];
            int row = wq * 16 + (lane & 15);
            uint32_t aoff = row * 256 + ((((ks << 1) | (lane >> 4)) ^ (row & 7)) << 4);
            LDSM4(ah[0], ah[1], ah[2], ah[3], sQh + aoff);
            LDSM4(al[0], al[1], al[2], al[3], sQl + aoff);
            uint32_t bh[4][2][2], bl[4][2][2];
            #pragma unroll
            for (int g = 0; g < 4; g++) {
                int n = g * 16 + ((lane >> 4) << 3) + (lane & 7);
                uint32_t boff = n * 256 + ((((ks << 1) | ((lane >> 3) & 1)) ^ (n & 7)) << 4);
                LDSM4(bh[g][0][0], bh[g][0][1], bh[g][1][0], bh[g][1][1], sK + boff);
                LDSM4(bl[g][0][0], bl[g][0][1], bl[g][1][0], bl[g][1][1], sK + 16384 + boff);
            }
            #pragma unroll
            for (int g = 0; g < 4; g++) {
                MMA16816F(sc[2*g],   ah, bh[g][0]);
                MMA16816F(sc[2*g+1], ah, bh[g][1]);
            }
            #pragma unroll
            for (int g = 0; g < 4; g++) {
                MMA16816F(sc[2*g],   ah, bl[g][0]);
                MMA16816F(sc[2*g+1], ah, bl[g][1]);
            }
            #pragma unroll
            for (int g = 0; g < 4; g++) {
                MMA16816F(sc[2*g],   al, bh[g][0]);
                MMA16816F(sc[2*g+1], al, bh[g][1]);
            }
        }

        // ---- causal mask (scale pre-folded into q) ----
        const int qrow0 = qt * 128 + wq * 16 + (lane >> 2);
        if (kt >= 2 * qt) {
            const int kcol0 = kt * 64 + 2 * (lane & 3);
            #pragma unroll
            for (int t = 0; t < 8; t++) {
                int c = kcol0 + 8 * t;
                if (c     > qrow0    ) sc[t][0] = -1e30f;
                if (c + 1 > qrow0    ) sc[t][1] = -1e30f;
                if (c     > qrow0 + 8) sc[t][2] = -1e30f;
                if (c + 1 > qrow0 + 8) sc[t][3] = -1e30f;
            }
        }

        // ---- online softmax ----
        float mx0 = -1e30f, mx1 = -1e30f;
        #pragma unroll
        for (int t = 0; t < 8; t++) {
            mx0 = fmaxf(mx0, fmaxf(sc[t][0], sc[t][1]));
            mx1 = fmaxf(mx1, fmaxf(sc[t][2], sc[t][3]));
        }
        mx0 = fmaxf(mx0, __shfl_xor_sync(0xffffffffu, mx0, 1));
        mx0 = fmaxf(mx0, __shfl_xor_sync(0xffffffffu, mx0, 2));
        mx1 = fmaxf(mx1, __shfl_xor_sync(0xffffffffu, mx1, 1));
        mx1 = fmaxf(mx1, __shfl_xor_sync(0xffffffffu, mx1, 2));
        float mn0 = fmaxf(m0, mx0), mn1 = fmaxf(m1, mx1);
        float a0 = __expf(m0 - mn0), a1 = __expf(m1 - mn1);
        m0 = mn0; m1 = mn1;
        float s0 = 0.f, s1 = 0.f;
        #pragma unroll
        for (int t = 0; t < 8; t++) {
            sc[t][0] = __expf(sc[t][0] - mn0);
            sc[t][1] = __expf(sc[t][1] - mn0);
            sc[t][2] = __expf(sc[t][2] - mn1);
            sc[t][3] = __expf(sc[t][3] - mn1);
            s0 += sc[t][0] + sc[t][1];
            s1 += sc[t][2] + sc[t][3];
        }
        s0 += __shfl_xor_sync(0xffffffffu, s0, 1);
        s0 += __shfl_xor_sync(0xffffffffu, s0, 2);
        s1 += __shfl_xor_sync(0xffffffffu, s1, 1);
        s1 += __shfl_xor_sync(0xffffffffu, s1, 2);
        l0 = l0 * a0 + s0;
        l1 = l1 * a1 + s1;
        #pragma unroll
        for (int t = 0; t < 16; t++) {
            out[t][0] *= a0; out[t][1] *= a0;
            out[t][2] *= a1; out[t][3] *= a1;
        }

        // ---- O += P V ----
        #pragma unroll
        for (int ks = 0; ks < 4; ks++) {
            uint32_t pa[4];
            pa[0] = pack_h2(sc[2*ks][0],   sc[2*ks][1]);
            pa[1] = pack_h2(sc[2*ks][2],   sc[2*ks][3]);
            pa[2] = pack_h2(sc[2*ks+1][0], sc[2*ks+1][1]);
            pa[3] = pack_h2(sc[2*ks+1][2], sc[2*ks+1][3]);
            int j = 16 * ks + (lane & 15);
            #pragma unroll
            for (int dg = 0; dg < 8; dg++) {
                uint32_t voff = j * 256 + ((((dg << 1) | (lane >> 4)) ^ (j & 7)) << 4);
                uint32_t vb[2][2];
                LDSM4T(vb[0][0], vb[0][1], vb[1][0], vb[1][1], sV + voff);
                MMA16816F(out[2*dg],   pa, vb[0]);
                MMA16816F(out[2*dg+1], pa, vb[1]);
            }
        }
        cstage = (cstage == 2) ? 0 : cstage + 1;
        pstage = (pstage == 2) ? 0 : pstage + 1;
    }

    // ---- epilogue: write hi/lo fp16 directly ----
    float il0 = 1.f / l0, il1 = 1.f / l1;
    int r0g = tokQ + wq * 16 + (lane >> 2);
    size_t base0 = (size_t)r0g * DM + h * DHEAD + 2 * (lane & 3);
    size_t base1 = base0 + (size_t)8 * DM;
    #pragma unroll
    for (int t = 0; t < 16; t++) {
        float o00 = out[t][0] * il0, o01 = out[t][1] * il0;
        float o10 = out[t][2] * il1, o11 = out[t][3] * il1;
        __half h00 = __float2half_rn(o00), h01 = __float2half_rn(o01);
        __half h10 = __float2half_rn(o10), h11 = __float2half_rn(o11);
        *(__half2*)(Ohi + base0 + t * 8) = __half2(h00, h01);
        *(__half2*)(Ohi + base1 + t * 8) = __half2(h10, h11);
        *(__half2*)(Olo + base0 + t * 8) =
            __half2(__float2half_rn(o00 - __half2float(h00)),
                    __float2half_rn(o01 - __half2float(h01)));
        *(__half2*)(Olo + base1 + t * 8) =
            __half2(__float2half_rn(o10 - __half2float(h10)),
                    __float2half_rn(o11 - __half2float(h11)));
    }
}

// ---------------- launch ----------------
extern "C" void kernel_launch(void* const* d_in, const int* in_sizes, int n_in,
                              void* d_out, int out_size)
{
    const float* x   = (const float*)d_in[0];
    const float* Wq  = (const float*)d_in[1];
    const float* Wk  = (const float*)d_in[2];
    const float* Wv  = (const float*)d_in[3];
    const float* Wo  = (const float*)d_in[4];
    const float* kvc = (const float*)d_in[5];
    const int*   bt  = (const int*)d_in[7];
    float* out = (float*)d_out;
    float* cache_out = out + (size_t)T_TOK * DM;

    __half *hi, *lo, *qhl, *wh, *khi, *klo, *vh;
    cudaGetSymbolAddress((void**)&hi,  g_hi);
    cudaGetSymbolAddress((void**)&lo,  g_lo);
    cudaGetSymbolAddress((void**)&qhl, g_qhl);
    cudaGetSymbolAddress((void**)&wh,  g_wh);
    cudaGetSymbolAddress((void**)&khi, g_khi);
    cudaGetSymbolAddress((void**)&klo, g_klo);
    cudaGetSymbolAddress((void**)&vh,  g_vh);
    __half* qhi = qhl;
    __half* qlo = qhl + (size_t)T_TOK * DM;

    cudaFuncSetAttribute(gemm_fp16x2, cudaFuncAttributeMaxDynamicSharedMemorySize, GEMM_SMEM);
    cudaFuncSetAttribute(flash_attn_hmma, cudaFuncAttributeMaxDynamicSharedMemorySize, FAH_SMEM);

    const int nx4 = T_TOK * DM / 4;
    const int nw4 = DM * DM / 4;
    const size_t wstride = (size_t)DM * DM;

    rope_table_kernel<<<SEQ * 64 / 256, 256>>>();

    split_fp16_kernel<<<nx4 / 256, 256>>>(x, hi, lo, nx4);
    conv_fp16_kernel<<<nw4 / 256, 256>>>(Wq, wh,               nw4);
    conv_fp16_kernel<<<nw4 / 256, 256>>>(Wk, wh + wstride,     nw4);
    conv_fp16_kernel<<<nw4 / 256, 256>>>(Wv, wh + 2 * wstride, nw4);

    // blocks 0..31 fully overwritten by the fused epilogue; copy only 32..63
    {
        const size_t half_elems = (size_t)32 * 2 * NH * 256 * DHEAD;
        cudaMemcpyAsync(cache_out + half_elems, kvc + half_elems,
                        half_elems * sizeof(float), cudaMemcpyDeviceToDevice);
    }

    // fused QKV GEMM + rope + scatter + fp16 prep: grid.x = 48
    gemm_fp16x2<<<dim3(48, T_TOK / 128), 256, GEMM_SMEM>>>(
        hi, lo, wh, nullptr, qhi, qlo, khi, klo, vh, cache_out, bt, 1);

    // attention writes hi/lo directly into g_hi/g_lo (x no longer needed)
    flash_attn_hmma<<<dim3(SEQ / 128, NH, NSEQ), 256, FAH_SMEM>>>(
        qhi, qlo, khi, klo, vh, hi, lo);

    conv_fp16_kernel<<<nw4 / 256, 256>>>(Wo, wh, nw4);
    gemm_fp16x2<<<dim3(16, T_TOK / 128), 256, GEMM_SMEM>>>(
        hi, lo, wh, out, nullptr, nullptr, nullptr, nullptr, nullptr, nullptr, nullptr, 0);
}

// round 13
// speedup vs baseline: 1.1202x; 1.1202x over previous
#include <cuda_runtime.h>
#include <cuda_bf16.h>
#include <cuda_fp16.h>
#include <math.h>
#include <stdint.h>

#define T_TOK 8192
#define DM    2048
#define NH    16
#define DHEAD 128
#define SEQ   1024
#define NSEQ  8
#define GK    2048
#define QSCALE 0.08838834764831845f

// ---------------- scratch (static __device__, allocation-free) ----------------
__device__ float g_q[(size_t)T_TOK * DM];
__device__ float g_k[(size_t)T_TOK * DM];
__device__ float g_v[(size_t)T_TOK * DM];
__device__ __half g_aoh[(size_t)T_TOK * DM];     // attention out, single fp16
__device__ float g_cos[SEQ * 64];
__device__ float g_sin[SEQ * 64];
__device__ __half g_hi[(size_t)T_TOK * DM];      // x-hi, then q-hi
__device__ __half g_lo[(size_t)T_TOK * DM];      // x-lo, then q-lo
__device__ __half g_wh[(size_t)3 * DM * DM];     // fp16 weights (Wq|Wk|Wv or Wo)
__device__ __half g_khi[(size_t)T_TOK * DM];
__device__ __half g_vh[(size_t)T_TOK * DM];

// ---------------- helpers ----------------
__device__ __forceinline__ uint32_t smem_u32(const void* p) {
    uint32_t a;
    asm("{ .reg .u64 t; cvta.to.shared.u64 t, %1; cvt.u32.u64 %0, t; }" : "=r"(a) : "l"(p));
    return a;
}
template<int N> __device__ __forceinline__ void cp_wait() {
    asm volatile("cp.async.wait_group %0;" :: "n"(N) : "memory");
}
__device__ __forceinline__ void cp_commit() {
    asm volatile("cp.async.commit_group;" ::: "memory");
}
__device__ __forceinline__ void cp_async16(uint32_t saddr, const void* gaddr) {
    asm volatile("cp.async.cg.shared.global [%0], [%1], 16;" :: "r"(saddr), "l"(gaddr));
}
#define LDSM4(r0, r1, r2, r3, addr) \
    asm volatile("ldmatrix.sync.aligned.m8n8.x4.shared.b16 {%0,%1,%2,%3}, [%4];" \
        : "=r"(r0), "=r"(r1), "=r"(r2), "=r"(r3) : "r"(addr))
#define LDSM4T(r0, r1, r2, r3, addr) \
    asm volatile("ldmatrix.sync.aligned.m8n8.x4.trans.shared.b16 {%0,%1,%2,%3}, [%4];" \
        : "=r"(r0), "=r"(r1), "=r"(r2), "=r"(r3) : "r"(addr))
#define MMA16816F(d, a, b) \
    asm volatile("mma.sync.aligned.m16n8k16.row.col.f32.f16.f16.f32 " \
        "{%0,%1,%2,%3}, {%4,%5,%6,%7}, {%8,%9}, {%0,%1,%2,%3};" \
        : "+f"((d)[0]), "+f"((d)[1]), "+f"((d)[2]), "+f"((d)[3]) \
        : "r"((a)[0]), "r"((a)[1]), "r"((a)[2]), "r"((a)[3]), "r"((b)[0]), "r"((b)[1]))

__device__ __forceinline__ uint32_t pack_h2(float a, float b) {
    __half2 h = __floats2half2_rn(a, b);
    return *reinterpret_cast<uint32_t*>(&h);
}

// ---------------- fp16 hi/lo split ----------------
__global__ __launch_bounds__(256) void split_fp16_kernel(
    const float* __restrict__ in, __half* __restrict__ hi,
    __half* __restrict__ lo, int n4)
{
    int i = blockIdx.x * blockDim.x + threadIdx.x;
    if (i >= n4) return;
    float4 v = ((const float4*)in)[i];
    __half h0 = __float2half_rn(v.x), h1 = __float2half_rn(v.y);
    __half h2 = __float2half_rn(v.z), h3 = __float2half_rn(v.w);
    __half l0 = __float2half_rn(v.x - __half2float(h0));
    __half l1 = __float2half_rn(v.y - __half2float(h1));
    __half l2 = __float2half_rn(v.z - __half2float(h2));
    __half l3 = __float2half_rn(v.w - __half2float(h3));
    ((__half2*)hi)[2*i]   = __half2(h0, h1);
    ((__half2*)hi)[2*i+1] = __half2(h2, h3);
    ((__half2*)lo)[2*i]   = __half2(l0, l1);
    ((__half2*)lo)[2*i+1] = __half2(l2, l3);
}

// ---------------- fp16 plain convert ----------------
__global__ __launch_bounds__(256) void conv_fp16_kernel(
    const float* __restrict__ in, __half* __restrict__ out, int n4)
{
    int i = blockIdx.x * blockDim.x + threadIdx.x;
    if (i >= n4) return;
    float4 v = ((const float4*)in)[i];
    ((__half2*)out)[2*i]   = __floats2half2_rn(v.x, v.y);
    ((__half2*)out)[2*i+1] = __floats2half2_rn(v.z, v.w);
}

// ---------------- RoPE cos/sin table ----------------
__global__ void rope_table_kernel() {
    int i = blockIdx.x * blockDim.x + threadIdx.x;
    int pos = i >> 6, j = i & 63;
    float inv = exp2f(-(float)j * 0.2076205059304593f);
    float ang = (float)pos * inv;
    float s, c;
    sincosf(ang, &s, &c);
    g_cos[i] = c;
    g_sin[i] = s;
}

// ------- HMMA fp16 GEMM: 256 thr, warp tile 64x32, 1- or 2-term -------
// layout per stage: Ahi | B | Alo(optional)
#define BK 64
#define NCHUNK (GK / BK)
#define TILE_B 16384
#define STAGE_B (3 * TILE_B)      // 49152 (2-term); 1-term uses only first 2 tiles
#define GEMM_SMEM (3 * STAGE_B)   // 147456

__global__ __launch_bounds__(256, 1) void gemm_fp16(
    const __half* __restrict__ Ahi, const __half* __restrict__ Alo,
    const __half* __restrict__ B,
    float* __restrict__ C0, float* __restrict__ C1, float* __restrict__ C2,
    int three, int two)
{
    extern __shared__ __align__(1024) char smraw[];
    const uint32_t smb = smem_u32(smraw);
    const int tid = threadIdx.x;
    const int lane = tid & 31, wid = tid >> 5;
    const int wm = wid >> 2, wn = wid & 3;            // warp grid 2(M) x 4(N)
    const int bx = blockIdx.x;
    const int brow = bx * 128;                        // row into weight buffer
    const int bm = blockIdx.y * 128;
    const int col = (bx & 15) * 128;                  // output column
    float* Cd = three ? ((bx >> 4) == 0 ? C0 : ((bx >> 4) == 1 ? C1 : C2)) : C0;

    const __half* srcs[3] = { Ahi + (size_t)bm * GK, B + (size_t)brow * GK,
                              two ? (Alo + (size_t)bm * GK) : (Ahi + (size_t)bm * GK) };
    const int ntile = two ? 3 : 2;

    float acc[4][4][4];
    #pragma unroll
    for (int mt = 0; mt < 4; mt++)
        #pragma unroll
        for (int nt = 0; nt < 4; nt++)
            #pragma unroll
            for (int j = 0; j < 4; j++) acc[mt][nt][j] = 0.f;

    auto prefetch = [&](int chunk_idx, int stg) {
        const uint32_t stb = smb + stg * STAGE_B;
        const int k0 = chunk_idx * BK;
        for (int tile = 0; tile < ntile; tile++) {
            const __half* g = srcs[tile] + k0;
            const uint32_t sbase = stb + tile * TILE_B;
            #pragma unroll
            for (int i = 0; i < 4; i++) {
                int idx = tid + 256 * i;
                int r = idx >> 3, c = idx & 7;
                uint32_t so = sbase + r * 128 + ((c ^ (r & 7)) << 4);
                cp_async16(so, g + (size_t)r * GK + c * 8);
            }
        }
    };

    prefetch(0, 0); cp_commit();
    prefetch(1, 1); cp_commit();

    int cstage = 0, pstage = 2;
    for (int i = 0; i < NCHUNK; i++) {
        if (i + 1 < NCHUNK) cp_wait<1>(); else cp_wait<0>();
        __syncthreads();
        if (i + 2 < NCHUNK) { prefetch(i + 2, pstage); cp_commit(); }

        const uint32_t stb = smb + cstage * STAGE_B;
        #pragma unroll
        for (int ks = 0; ks < 4; ks++) {
            uint32_t af[2][4][4];
            uint32_t bf[4][2];
            #pragma unroll
            for (int mt = 0; mt < 4; mt++) {
                int row = wm * 64 + mt * 16 + (lane & 15);
                uint32_t ad = stb + row * 128 + ((((ks << 1) | (lane >> 4)) ^ (row & 7)) << 4);
                LDSM4(af[0][mt][0], af[0][mt][1], af[0][mt][2], af[0][mt][3], ad);
                if (two)
                    LDSM4(af[1][mt][0], af[1][mt][1], af[1][mt][2], af[1][mt][3],
                          ad + 2 * TILE_B);
            }
            #pragma unroll
            for (int nt2 = 0; nt2 < 2; nt2++) {
                int n = wn * 32 + nt2 * 16 + ((lane >> 4) << 3) + (lane & 7);
                uint32_t bd = stb + TILE_B + n * 128
                            + ((((ks << 1) | ((lane >> 3) & 1)) ^ (n & 7)) << 4);
                LDSM4(bf[nt2*2][0], bf[nt2*2][1], bf[nt2*2+1][0], bf[nt2*2+1][1], bd);
            }
            #pragma unroll
            for (int mt = 0; mt < 4; mt++)
                #pragma unroll
                for (int nt = 0; nt < 4; nt++)
                    MMA16816F(acc[mt][nt], af[0][mt], bf[nt]);   // hi*B
            if (two) {
                #pragma unroll
                for (int mt = 0; mt < 4; mt++)
                    #pragma unroll
                    for (int nt = 0; nt < 4; nt++)
                        MMA16816F(acc[mt][nt], af[1][mt], bf[nt]);   // lo*B
            }
        }
        cstage = (cstage == 2) ? 0 : cstage + 1;
        pstage = (pstage == 2) ? 0 : pstage + 1;
    }

    #pragma unroll
    for (int mt = 0; mt < 4; mt++) {
        int r0 = bm + wm * 64 + mt * 16 + (lane >> 2);
        #pragma unroll
        for (int nt = 0; nt < 4; nt++) {
            int c0 = col + wn * 32 + nt * 8 + ((lane & 3) << 1);
            float* cp = Cd + (size_t)r0 * DM + c0;
            *(float2*)cp = make_float2(acc[mt][nt][0], acc[mt][nt][1]);
            *(float2*)(cp + (size_t)8 * DM) = make_float2(acc[mt][nt][2], acc[mt][nt][3]);
        }
    }
}

// ------ fused RoPE + paged KV scatter + fp16 attention prep (q scaled) ------
__global__ __launch_bounds__(256) void rope_scatter_prep(
    const float* __restrict__ q, const float* __restrict__ k,
    const float* __restrict__ v, const int* __restrict__ btab,
    float* __restrict__ cache,
    __half* __restrict__ qhi, __half* __restrict__ qlo,
    __half* __restrict__ khi, __half* __restrict__ vh)
{
    const int t   = blockIdx.x;
    const int pos = t & (SEQ - 1);
    const int seq = t >> 10;
    const int phys = btab[seq * 4 + (pos >> 8)];
    const int off  = pos & 255;
    const size_t tb = (size_t)t * DM;

    #pragma unroll
    for (int p = threadIdx.x; p < NH * 64; p += 256) {
        int h = p >> 6, j = p & 63;
        float c = g_cos[pos * 64 + j];
        float s = g_sin[pos * 64 + j];
        size_t base = tb + h * 128 + j;

        float q0 = q[base], q1 = q[base + 64];
        float nq0 = (q0 * c - q1 * s) * QSCALE;
        float nq1 = (q1 * c + q0 * s) * QSCALE;
        __half qh0 = __float2half_rn(nq0);
        __half qh1 = __float2half_rn(nq1);
        qhi[base]      = qh0; qlo[base]      = __float2half_rn(nq0 - __half2float(qh0));
        qhi[base + 64] = qh1; qlo[base + 64] = __float2half_rn(nq1 - __half2float(qh1));

        float k0 = k[base], k1 = k[base + 64];
        float nk0 = k0 * c - k1 * s;
        float nk1 = k1 * c + k0 * s;
        khi[base]      = __float2half_rn(nk0);
        khi[base + 64] = __float2half_rn(nk1);

        size_t cb = ((size_t)(phys * 32 + h) * 256 + off) * 128 + j;
        cache[cb]      = nk0;
        cache[cb + 64] = nk1;
    }
    #pragma unroll
    for (int e = threadIdx.x; e < DM; e += 256) {
        int h = e >> 7, d = e & 127;
        float vv = v[tb + e];
        size_t cb = ((size_t)(phys * 32 + 16 + h) * 256 + off) * 128 + d;
        cache[cb] = vv;
        vh[tb + e] = __float2half_rn(vv);
    }
}

// ---------------- flash attention, HMMA fp16 (2-term QK), 3-stage ----------------
// Q: 64KB at smb; stages at smb+65536 + st*32768: Kh 16K | V 16K
#define FAH_SMEM 163840

__global__ __launch_bounds__(256, 1) void flash_attn_hmma(
    const __half* __restrict__ Qhg, const __half* __restrict__ Qlg,
    const __half* __restrict__ Khg, const __half* __restrict__ Vhg,
    __half* __restrict__ Oh)
{
    extern __shared__ __align__(1024) char sm[];
    const uint32_t smb = smem_u32(sm);
    const uint32_t sQh = smb, sQl = smb + 32768;
    const int tid = threadIdx.x, lane = tid & 31, wq = tid >> 5;
    const int qt = (int)(gridDim.x - 1 - blockIdx.x);   // heavy tiles first
    const int h = blockIdx.y, b = blockIdx.z;
    const int tokQ = b * SEQ + qt * 128;
    const int nkt = 2 * qt + 2;

    auto load_kv = [&](int kt, int stg) {
        uint32_t st = smb + 65536 + stg * 32768;
        const __half* gh = Khg + (size_t)(b * SEQ + kt * 64) * DM + h * DHEAD;
        const __half* gv = Vhg + (size_t)(b * SEQ + kt * 64) * DM + h * DHEAD;
        #pragma unroll
        for (int i = 0; i < 4; i++) {
            int idx = tid + 256 * i;
            int r = idx >> 4, c = idx & 15;
            uint32_t off = r * 256 + ((c ^ (r & 7)) << 4);
            cp_async16(st + off, gh + (size_t)r * DM + c * 8);
            cp_async16(st + 16384 + off, gv + (size_t)r * DM + c * 8);
        }
    };

    {
        const __half* gq = Qhg + (size_t)tokQ * DM + h * DHEAD;
        const __half* gl = Qlg + (size_t)tokQ * DM + h * DHEAD;
        #pragma unroll
        for (int i = 0; i < 8; i++) {
            int idx = tid + 256 * i;
            int r = idx >> 4, c = idx & 15;
            uint32_t off = r * 256 + ((c ^ (r & 7)) << 4);
            cp_async16(sQh + off, gq + (size_t)r * DM + c * 8);
            cp_async16(sQl + off, gl + (size_t)r * DM + c * 8);
        }
    }
    load_kv(0, 0); cp_commit();
    load_kv(1, 1); cp_commit();

    float m0 = -1e30f, m1 = -1e30f, l0 = 0.f, l1 = 0.f;
    float out[16][4];
    #pragma unroll
    for (int t = 0; t < 16; t++)
        #pragma unroll
        for (int j = 0; j < 4; j++) out[t][j] = 0.f;

    int cstage = 0, pstage = 2;
    for (int kt = 0; kt < nkt; kt++) {
        if (kt + 1 < nkt) cp_wait<1>(); else cp_wait<0>();
        __syncthreads();
        if (kt + 2 < nkt) { load_kv(kt + 2, pstage); cp_commit(); }

        const uint32_t sK = smb + 65536 + cstage * 32768;
        const uint32_t sV = sK + 16384;

        // ---- S = Q K^T (q hi/lo, k single; term-major) ----
        float sc[8][4];
        #pragma unroll
        for (int t = 0; t < 8; t++)
            #pragma unroll
            for (int j = 0; j < 4; j++) sc[t][j] = 0.f;

        #pragma unroll
        for (int ks = 0; ks < 8; ks++) {
            uint32_t ah[4], al[4];
            int row = wq * 16 + (lane & 15);
            uint32_t aoff = row * 256 + ((((ks << 1) | (lane >> 4)) ^ (row & 7)) << 4);
            LDSM4(ah[0], ah[1], ah[2], ah[3], sQh + aoff);
            LDSM4(al[0], al[1], al[2], al[3], sQl + aoff);
            uint32_t bh[4][2][2];
            #pragma unroll
            for (int g = 0; g < 4; g++) {
                int n = g * 16 + ((lane >> 4) << 3) + (lane & 7);
                uint32_t boff = n * 256 + ((((ks << 1) | ((lane >> 3) & 1)) ^ (n & 7)) << 4);
                LDSM4(bh[g][0][0], bh[g][0][1], bh[g][1][0], bh[g][1][1], sK + boff);
            }
            #pragma unroll
            for (int g = 0; g < 4; g++) {
                MMA16816F(sc[2*g],   ah, bh[g][0]);
                MMA16816F(sc[2*g+1], ah, bh[g][1]);
            }
            #pragma unroll
            for (int g = 0; g < 4; g++) {
                MMA16816F(sc[2*g],   al, bh[g][0]);
                MMA16816F(sc[2*g+1], al, bh[g][1]);
            }
        }

        // ---- causal mask (scale pre-folded into q) ----
        const int qrow0 = qt * 128 + wq * 16 + (lane >> 2);
        if (kt >= 2 * qt) {
            const int kcol0 = kt * 64 + 2 * (lane & 3);
            #pragma unroll
            for (int t = 0; t < 8; t++) {
                int c = kcol0 + 8 * t;
                if (c     > qrow0    ) sc[t][0] = -1e30f;
                if (c + 1 > qrow0    ) sc[t][1] = -1e30f;
                if (c     > qrow0 + 8) sc[t][2] = -1e30f;
                if (c + 1 > qrow0 + 8) sc[t][3] = -1e30f;
            }
        }

        // ---- online softmax ----
        float mx0 = -1e30f, mx1 = -1e30f;
        #pragma unroll
        for (int t = 0; t < 8; t++) {
            mx0 = fmaxf(mx0, fmaxf(sc[t][0], sc[t][1]));
            mx1 = fmaxf(mx1, fmaxf(sc[t][2], sc[t][3]));
        }
        mx0 = fmaxf(mx0, __shfl_xor_sync(0xffffffffu, mx0, 1));
        mx0 = fmaxf(mx0, __shfl_xor_sync(0xffffffffu, mx0, 2));
        mx1 = fmaxf(mx1, __shfl_xor_sync(0xffffffffu, mx1, 1));
        mx1 = fmaxf(mx1, __shfl_xor_sync(0xffffffffu, mx1, 2));
        float mn0 = fmaxf(m0, mx0), mn1 = fmaxf(m1, mx1);
        float a0 = __expf(m0 - mn0), a1 = __expf(m1 - mn1);
        m0 = mn0; m1 = mn1;
        float s0 = 0.f, s1 = 0.f;
        #pragma unroll
        for (int t = 0; t < 8; t++) {
            sc[t][0] = __expf(sc[t][0] - mn0);
            sc[t][1] = __expf(sc[t][1] - mn0);
            sc[t][2] = __expf(sc[t][2] - mn1);
            sc[t][3] = __expf(sc[t][3] - mn1);
            s0 += sc[t][0] + sc[t][1];
            s1 += sc[t][2] + sc[t][3];
        }
        s0 += __shfl_xor_sync(0xffffffffu, s0, 1);
        s0 += __shfl_xor_sync(0xffffffffu, s0, 2);
        s1 += __shfl_xor_sync(0xffffffffu, s1, 1);
        s1 += __shfl_xor_sync(0xffffffffu, s1, 2);
        l0 = l0 * a0 + s0;
        l1 = l1 * a1 + s1;
        #pragma unroll
        for (int t = 0; t < 16; t++) {
            out[t][0] *= a0; out[t][1] *= a0;
            out[t][2] *= a1; out[t][3] *= a1;
        }

        // ---- O += P V ----
        #pragma unroll
        for (int ks = 0; ks < 4; ks++) {
            uint32_t pa[4];
            pa[0] = pack_h2(sc[2*ks][0],   sc[2*ks][1]);
            pa[1] = pack_h2(sc[2*ks][2],   sc[2*ks][3]);
            pa[2] = pack_h2(sc[2*ks+1][0], sc[2*ks+1][1]);
            pa[3] = pack_h2(sc[2*ks+1][2], sc[2*ks+1][3]);
            int j = 16 * ks + (lane & 15);
            #pragma unroll
            for (int dg = 0; dg < 8; dg++) {
                uint32_t voff = j * 256 + ((((dg << 1) | (lane >> 4)) ^ (j & 7)) << 4);
                uint32_t vb[2][2];
                LDSM4T(vb[0][0], vb[0][1], vb[1][0], vb[1][1], sV + voff);
                MMA16816F(out[2*dg],   pa, vb[0]);
                MMA16816F(out[2*dg+1], pa, vb[1]);
            }
        }
        cstage = (cstage == 2) ? 0 : cstage + 1;
        pstage = (pstage == 2) ? 0 : pstage + 1;
    }

    // ---- epilogue: single fp16 out ----
    float il0 = 1.f / l0, il1 = 1.f / l1;
    int r0g = tokQ + wq * 16 + (lane >> 2);
    size_t base0 = (size_t)r0g * DM + h * DHEAD + 2 * (lane & 3);
    size_t base1 = base0 + (size_t)8 * DM;
    #pragma unroll
    for (int t = 0; t < 16; t++) {
        *(__half2*)(Oh + base0 + t * 8) =
            __floats2half2_rn(out[t][0] * il0, out[t][1] * il0);
        *(__half2*)(Oh + base1 + t * 8) =
            __floats2half2_rn(out[t][2] * il1, out[t][3] * il1);
    }
}

// ---------------- launch ----------------
extern "C" void kernel_launch(void* const* d_in, const int* in_sizes, int n_in,
                              void* d_out, int out_size)
{
    const float* x   = (const float*)d_in[0];
    const float* Wq  = (const float*)d_in[1];
    const float* Wk  = (const float*)d_in[2];
    const float* Wv  = (const float*)d_in[3];
    const float* Wo  = (const float*)d_in[4];
    const float* kvc = (const float*)d_in[5];
    const int*   bt  = (const int*)d_in[7];
    float* out = (float*)d_out;
    float* cache_out = out + (size_t)T_TOK * DM;

    float *qp, *kp, *vp;
    __half *aoh, *hi, *lo, *wh, *khi, *vh;
    cudaGetSymbolAddress((void**)&qp,  g_q);
    cudaGetSymbolAddress((void**)&kp,  g_k);
    cudaGetSymbolAddress((void**)&vp,  g_v);
    cudaGetSymbolAddress((void**)&aoh, g_aoh);
    cudaGetSymbolAddress((void**)&hi,  g_hi);
    cudaGetSymbolAddress((void**)&lo,  g_lo);
    cudaGetSymbolAddress((void**)&wh,  g_wh);
    cudaGetSymbolAddress((void**)&khi, g_khi);
    cudaGetSymbolAddress((void**)&vh,  g_vh);

    cudaFuncSetAttribute(gemm_fp16, cudaFuncAttributeMaxDynamicSharedMemorySize, GEMM_SMEM);
    cudaFuncSetAttribute(flash_attn_hmma, cudaFuncAttributeMaxDynamicSharedMemorySize, FAH_SMEM);

    const int nx4 = T_TOK * DM / 4;
    const int nw4 = DM * DM / 4;
    const size_t wstride = (size_t)DM * DM;

    rope_table_kernel<<<SEQ * 64 / 256, 256>>>();

    split_fp16_kernel<<<nx4 / 256, 256>>>(x, hi, lo, nx4);
    conv_fp16_kernel<<<nw4 / 256, 256>>>(Wq, wh,               nw4);
    conv_fp16_kernel<<<nw4 / 256, 256>>>(Wk, wh + wstride,     nw4);
    conv_fp16_kernel<<<nw4 / 256, 256>>>(Wv, wh + 2 * wstride, nw4);

    // fused QKV GEMM (2-term): grid.x = 48
    gemm_fp16<<<dim3(48, T_TOK / 128), 256, GEMM_SMEM>>>(
        hi, lo, wh, qp, kp, vp, 1, 1);

    // blocks 0..31 fully overwritten by scatter; copy only blocks 32..63
    {
        const size_t half_elems = (size_t)32 * 2 * NH * 256 * DHEAD;
        cudaMemcpyAsync(cache_out + half_elems, kvc + half_elems,
                        half_elems * sizeof(float), cudaMemcpyDeviceToDevice);
    }

    // rope + scatter + fp16 prep (q hi/lo overwrite x hi/lo; k single fp16)
    rope_scatter_prep<<<T_TOK, 256>>>(qp, kp, vp, bt, cache_out,
                                      hi, lo, khi, vh);

    flash_attn_hmma<<<dim3(SEQ / 128, NH, NSEQ), 256, FAH_SMEM>>>(
        hi, lo, khi, vh, aoh);

    conv_fp16_kernel<<<nw4 / 256, 256>>>(Wo, wh, nw4);
    // Wo GEMM (1-term): A = attention out single fp16
    gemm_fp16<<<dim3(16, T_TOK / 128), 256, GEMM_SMEM>>>(
        aoh, nullptr, wh, out, nullptr, nullptr, 0, 0);
}

// round 15
// speedup vs baseline: 1.5336x; 1.3691x over previous
#include <cuda_runtime.h>
#include <cuda_bf16.h>
#include <cuda_fp16.h>
#include <math.h>
#include <stdint.h>

#define T_TOK 8192
#define DM    2048
#define NH    16
#define DHEAD 128
#define SEQ   1024
#define NSEQ  8
#define GK    2048
#define QSCALE 0.08838834764831845f

// ---------------- scratch (static __device__, allocation-free) ----------------
__device__ float g_q[(size_t)T_TOK * DM];
__device__ float g_k[(size_t)T_TOK * DM];
__device__ float g_v[(size_t)T_TOK * DM];
__device__ __half g_aoh[(size_t)T_TOK * DM];     // attention out, single fp16
__device__ float g_cos[SEQ * 64];
__device__ float g_sin[SEQ * 64];
__device__ __half g_hi[(size_t)T_TOK * DM];      // x (single fp16), then q-hi
__device__ __half g_lo[(size_t)T_TOK * DM];      // q-lo
__device__ __half g_wh[(size_t)3 * DM * DM];     // fp16 weights (Wq|Wk|Wv or Wo)
__device__ __half g_khi[(size_t)T_TOK * DM];
__device__ __half g_vh[(size_t)T_TOK * DM];

// ---------------- helpers ----------------
__device__ __forceinline__ uint32_t smem_u32(const void* p) {
    uint32_t a;
    asm("{ .reg .u64 t; cvta.to.shared.u64 t, %1; cvt.u32.u64 %0, t; }" : "=r"(a) : "l"(p));
    return a;
}
template<int N> __device__ __forceinline__ void cp_wait() {
    asm volatile("cp.async.wait_group %0;" :: "n"(N) : "memory");
}
__device__ __forceinline__ void cp_commit() {
    asm volatile("cp.async.commit_group;" ::: "memory");
}
__device__ __forceinline__ void cp_async16(uint32_t saddr, const void* gaddr) {
    asm volatile("cp.async.cg.shared.global [%0], [%1], 16;" :: "r"(saddr), "l"(gaddr));
}
#define LDSM4(r0, r1, r2, r3, addr) \
    asm volatile("ldmatrix.sync.aligned.m8n8.x4.shared.b16 {%0,%1,%2,%3}, [%4];" \
        : "=r"(r0), "=r"(r1), "=r"(r2), "=r"(r3) : "r"(addr))
#define LDSM4T(r0, r1, r2, r3, addr) \
    asm volatile("ldmatrix.sync.aligned.m8n8.x4.trans.shared.b16 {%0,%1,%2,%3}, [%4];" \
        : "=r"(r0), "=r"(r1), "=r"(r2), "=r"(r3) : "r"(addr))
#define MMA16816F(d, a, b) \
    asm volatile("mma.sync.aligned.m16n8k16.row.col.f32.f16.f16.f32 " \
        "{%0,%1,%2,%3}, {%4,%5,%6,%7}, {%8,%9}, {%0,%1,%2,%3};" \
        : "+f"((d)[0]), "+f"((d)[1]), "+f"((d)[2]), "+f"((d)[3]) \
        : "r"((a)[0]), "r"((a)[1]), "r"((a)[2]), "r"((a)[3]), "r"((b)[0]), "r"((b)[1]))

__device__ __forceinline__ uint32_t pack_h2(float a, float b) {
    __half2 h = __floats2half2_rn(a, b);
    return *reinterpret_cast<uint32_t*>(&h);
}

// ---------------- fp16 plain convert ----------------
__global__ __launch_bounds__(256) void conv_fp16_kernel(
    const float* __restrict__ in, __half* __restrict__ out, int n4)
{
    int i = blockIdx.x * blockDim.x + threadIdx.x;
    if (i >= n4) return;
    float4 v = ((const float4*)in)[i];
    ((__half2*)out)[2*i]   = __floats2half2_rn(v.x, v.y);
    ((__half2*)out)[2*i+1] = __floats2half2_rn(v.z, v.w);
}

// ---------------- RoPE cos/sin table ----------------
__global__ void rope_table_kernel() {
    int i = blockIdx.x * blockDim.x + threadIdx.x;
    int pos = i >> 6, j = i & 63;
    float inv = exp2f(-(float)j * 0.2076205059304593f);
    float ang = (float)pos * inv;
    float s, c;
    sincosf(ang, &s, &c);
    g_cos[i] = c;
    g_sin[i] = s;
}

// ------- HMMA fp16 GEMM: 256 thr, warp tile 64x32, 1- or 2-term -------
// layout per stage: Ahi | B | Alo(optional)
#define BK 64
#define NCHUNK (GK / BK)
#define TILE_B 16384
#define STAGE_B (3 * TILE_B)      // 49152 (2-term); 1-term uses only first 2 tiles
#define GEMM_SMEM (3 * STAGE_B)   // 147456

__global__ __launch_bounds__(256, 1) void gemm_fp16(
    const __half* __restrict__ Ahi, const __half* __restrict__ Alo,
    const __half* __restrict__ B,
    float* __restrict__ C0, float* __restrict__ C1, float* __restrict__ C2,
    int three, int two)
{
    extern __shared__ __align__(1024) char smraw[];
    const uint32_t smb = smem_u32(smraw);
    const int tid = threadIdx.x;
    const int lane = tid & 31, wid = tid >> 5;
    const int wm = wid >> 2, wn = wid & 3;            // warp grid 2(M) x 4(N)
    const int bx = blockIdx.x;
    const int brow = bx * 128;                        // row into weight buffer
    const int bm = blockIdx.y * 128;
    const int col = (bx & 15) * 128;                  // output column
    float* Cd = three ? ((bx >> 4) == 0 ? C0 : ((bx >> 4) == 1 ? C1 : C2)) : C0;

    const __half* srcs[3] = { Ahi + (size_t)bm * GK, B + (size_t)brow * GK,
                              two ? (Alo + (size_t)bm * GK) : (Ahi + (size_t)bm * GK) };
    const int ntile = two ? 3 : 2;

    float acc[4][4][4];
    #pragma unroll
    for (int mt = 0; mt < 4; mt++)
        #pragma unroll
        for (int nt = 0; nt < 4; nt++)
            #pragma unroll
            for (int j = 0; j < 4; j++) acc[mt][nt][j] = 0.f;

    auto prefetch = [&](int chunk_idx, int stg) {
        const uint32_t stb = smb + stg * STAGE_B;
        const int k0 = chunk_idx * BK;
        for (int tile = 0; tile < ntile; tile++) {
            const __half* g = srcs[tile] + k0;
            const uint32_t sbase = stb + tile * TILE_B;
            #pragma unroll
            for (int i = 0; i < 4; i++) {
                int idx = tid + 256 * i;
                int r = idx >> 3, c = idx & 7;
                uint32_t so = sbase + r * 128 + ((c ^ (r & 7)) << 4);
                cp_async16(so, g + (size_t)r * GK + c * 8);
            }
        }
    };

    prefetch(0, 0); cp_commit();
    prefetch(1, 1); cp_commit();

    int cstage = 0, pstage = 2;
    for (int i = 0; i < NCHUNK; i++) {
        if (i + 1 < NCHUNK) cp_wait<1>(); else cp_wait<0>();
        __syncthreads();
        if (i + 2 < NCHUNK) { prefetch(i + 2, pstage); cp_commit(); }

        const uint32_t stb = smb + cstage * STAGE_B;
        #pragma unroll
        for (int ks = 0; ks < 4; ks++) {
            uint32_t af[2][4][4];
            uint32_t bf[4][2];
            #pragma unroll
            for (int mt = 0; mt < 4; mt++) {
                int row = wm * 64 + mt * 16 + (lane & 15);
                uint32_t ad = stb + row * 128 + ((((ks << 1) | (lane >> 4)) ^ (row & 7)) << 4);
                LDSM4(af[0][mt][0], af[0][mt][1], af[0][mt][2], af[0][mt][3], ad);
                if (two)
                    LDSM4(af[1][mt][0], af[1][mt][1], af[1][mt][2], af[1][mt][3],
                          ad + 2 * TILE_B);
            }
            #pragma unroll
            for (int nt2 = 0; nt2 < 2; nt2++) {
                int n = wn * 32 + nt2 * 16 + ((lane >> 4) << 3) + (lane & 7);
                uint32_t bd = stb + TILE_B + n * 128
                            + ((((ks << 1) | ((lane >> 3) & 1)) ^ (n & 7)) << 4);
                LDSM4(bf[nt2*2][0], bf[nt2*2][1], bf[nt2*2+1][0], bf[nt2*2+1][1], bd);
            }
            #pragma unroll
            for (int mt = 0; mt < 4; mt++)
                #pragma unroll
                for (int nt = 0; nt < 4; nt++)
                    MMA16816F(acc[mt][nt], af[0][mt], bf[nt]);   // hi*B
            if (two) {
                #pragma unroll
                for (int mt = 0; mt < 4; mt++)
                    #pragma unroll
                    for (int nt = 0; nt < 4; nt++)
                        MMA16816F(acc[mt][nt], af[1][mt], bf[nt]);   // lo*B
            }
        }
        cstage = (cstage == 2) ? 0 : cstage + 1;
        pstage = (pstage == 2) ? 0 : pstage + 1;
    }

    #pragma unroll
    for (int mt = 0; mt < 4; mt++) {
        int r0 = bm + wm * 64 + mt * 16 + (lane >> 2);
        #pragma unroll
        for (int nt = 0; nt < 4; nt++) {
            int c0 = col + wn * 32 + nt * 8 + ((lane & 3) << 1);
            float* cp = Cd + (size_t)r0 * DM + c0;
            *(float2*)cp = make_float2(acc[mt][nt][0], acc[mt][nt][1]);
            *(float2*)(cp + (size_t)8 * DM) = make_float2(acc[mt][nt][2], acc[mt][nt][3]);
        }
    }
}

// ------ fused RoPE + paged KV scatter + fp16 attention prep (q scaled) ------
__global__ __launch_bounds__(256) void rope_scatter_prep(
    const float* __restrict__ q, const float* __restrict__ k,
    const float* __restrict__ v, const int* __restrict__ btab,
    float* __restrict__ cache,
    __half* __restrict__ qhi, __half* __restrict__ qlo,
    __half* __restrict__ khi, __half* __restrict__ vh)
{
    const int t   = blockIdx.x;
    const int pos = t & (SEQ - 1);
    const int seq = t >> 10;
    const int phys = btab[seq * 4 + (pos >> 8)];
    const int off  = pos & 255;
    const size_t tb = (size_t)t * DM;

    #pragma unroll
    for (int p = threadIdx.x; p < NH * 64; p += 256) {
        int h = p >> 6, j = p & 63;
        float c = g_cos[pos * 64 + j];
        float s = g_sin[pos * 64 + j];
        size_t base = tb + h * 128 + j;

        float q0 = q[base], q1 = q[base + 64];
        float nq0 = (q0 * c - q1 * s) * QSCALE;
        float nq1 = (q1 * c + q0 * s) * QSCALE;
        __half qh0 = __float2half_rn(nq0);
        __half qh1 = __float2half_rn(nq1);
        qhi[base]      = qh0; qlo[base]      = __float2half_rn(nq0 - __half2float(qh0));
        qhi[base + 64] = qh1; qlo[base + 64] = __float2half_rn(nq1 - __half2float(qh1));

        float k0 = k[base], k1 = k[base + 64];
        float nk0 = k0 * c - k1 * s;
        float nk1 = k1 * c + k0 * s;
        khi[base]      = __float2half_rn(nk0);
        khi[base + 64] = __float2half_rn(nk1);

        size_t cb = ((size_t)(phys * 32 + h) * 256 + off) * 128 + j;
        cache[cb]      = nk0;
        cache[cb + 64] = nk1;
    }
    #pragma unroll
    for (int e = threadIdx.x; e < DM; e += 256) {
        int h = e >> 7, d = e & 127;
        float vv = v[tb + e];
        size_t cb = ((size_t)(phys * 32 + 16 + h) * 256 + off) * 128 + d;
        cache[cb] = vv;
        vh[tb + e] = __float2half_rn(vv);
    }
}

// ---------------- flash attention, HMMA fp16 (2-term QK), 3-stage ----------------
// Q: 64KB at smb; stages at smb+65536 + st*32768: Kh 16K | V 16K
#define FAH_SMEM 163840

__global__ __launch_bounds__(256, 1) void flash_attn_hmma(
    const __half* __restrict__ Qhg, const __half* __restrict__ Qlg,
    const __half* __restrict__ Khg, const __half* __restrict__ Vhg,
    __half* __restrict__ Oh)
{
    extern __shared__ __align__(1024) char sm[];
    const uint32_t smb = smem_u32(sm);
    const uint32_t sQh = smb, sQl = smb + 32768;
    const int tid = threadIdx.x, lane = tid & 31, wq = tid >> 5;
    const int qt = (int)(gridDim.x - 1 - blockIdx.x);   // heavy tiles first
    const int h = blockIdx.y, b = blockIdx.z;
    const int tokQ = b * SEQ + qt * 128;
    const int nkt = 2 * qt + 2;

    auto load_kv = [&](int kt, int stg) {
        uint32_t st = smb + 65536 + stg * 32768;
        const __half* gh = Khg + (size_t)(b * SEQ + kt * 64) * DM + h * DHEAD;
        const __half* gv = Vhg + (size_t)(b * SEQ + kt * 64) * DM + h * DHEAD;
        #pragma unroll
        for (int i = 0; i < 4; i++) {
            int idx = tid + 256 * i;
            int r = idx >> 4, c = idx & 15;
            uint32_t off = r * 256 + ((c ^ (r & 7)) << 4);
            cp_async16(st + off, gh + (size_t)r * DM + c * 8);
            cp_async16(st + 16384 + off, gv + (size_t)r * DM + c * 8);
        }
    };

    {
        const __half* gq = Qhg + (size_t)tokQ * DM + h * DHEAD;
        const __half* gl = Qlg + (size_t)tokQ * DM + h * DHEAD;
        #pragma unroll
        for (int i = 0; i < 8; i++) {
            int idx = tid + 256 * i;
            int r = idx >> 4, c = idx & 15;
            uint32_t off = r * 256 + ((c ^ (r & 7)) << 4);
            cp_async16(sQh + off, gq + (size_t)r * DM + c * 8);
            cp_async16(sQl + off, gl + (size_t)r * DM + c * 8);
        }
    }
    load_kv(0, 0); cp_commit();
    load_kv(1, 1); cp_commit();

    float m0 = -1e30f, m1 = -1e30f, l0 = 0.f, l1 = 0.f;
    float out[16][4];
    #pragma unroll
    for (int t = 0; t < 16; t++)
        #pragma unroll
        for (int j = 0; j < 4; j++) out[t][j] = 0.f;

    int cstage = 0, pstage = 2;
    for (int kt = 0; kt < nkt; kt++) {
        if (kt + 1 < nkt) cp_wait<1>(); else cp_wait<0>();
        __syncthreads();
        if (kt + 2 < nkt) { load_kv(kt + 2, pstage); cp_commit(); }

        const uint32_t sK = smb + 65536 + cstage * 32768;
        const uint32_t sV = sK + 16384;

        // ---- S = Q K^T (q hi/lo, k single; term-major) ----
        float sc[8][4];
        #pragma unroll
        for (int t = 0; t < 8; t++)
            #pragma unroll
            for (int j = 0; j < 4; j++) sc[t][j] = 0.f;

        #pragma unroll
        for (int ks = 0; ks < 8; ks++) {
            uint32_t ah[4], al[4];
            int row = wq * 16 + (lane & 15);
            uint32_t aoff = row * 256 + ((((ks << 1) | (lane >> 4)) ^ (row & 7)) << 4);
            LDSM4(ah[0], ah[1], ah[2], ah[3], sQh + aoff);
            LDSM4(al[0], al[1], al[2], al[3], sQl + aoff);
            uint32_t bh[4][2][2];
            #pragma unroll
            for (int g = 0; g < 4; g++) {
                int n = g * 16 + ((lane >> 4) << 3) + (lane & 7);
                uint32_t boff = n * 256 + ((((ks << 1) | ((lane >> 3) & 1)) ^ (n & 7)) << 4);
                LDSM4(bh[g][0][0], bh[g][0][1], bh[g][1][0], bh[g][1][1], sK + boff);
            }
            #pragma unroll
            for (int g = 0; g < 4; g++) {
                MMA16816F(sc[2*g],   ah, bh[g][0]);
                MMA16816F(sc[2*g+1], ah, bh[g][1]);
            }
            #pragma unroll
            for (int g = 0; g < 4; g++) {
                MMA16816F(sc[2*g],   al, bh[g][0]);
                MMA16816F(sc[2*g+1], al, bh[g][1]);
            }
        }

        // ---- causal mask (scale pre-folded into q) ----
        const int qrow0 = qt * 128 + wq * 16 + (lane >> 2);
        if (kt >= 2 * qt) {
            const int kcol0 = kt * 64 + 2 * (lane & 3);
            #pragma unroll
            for (int t = 0; t < 8; t++) {
                int c = kcol0 + 8 * t;
                if (c     > qrow0    ) sc[t][0] = -1e30f;
                if (c + 1 > qrow0    ) sc[t][1] = -1e30f;
                if (c     > qrow0 + 8) sc[t][2] = -1e30f;
                if (c + 1 > qrow0 + 8) sc[t][3] = -1e30f;
            }
        }

        // ---- online softmax ----
        float mx0 = -1e30f, mx1 = -1e30f;
        #pragma unroll
        for (int t = 0; t < 8; t++) {
            mx0 = fmaxf(mx0, fmaxf(sc[t][0], sc[t][1]));
            mx1 = fmaxf(mx1, fmaxf(sc[t][2], sc[t][3]));
        }
        mx0 = fmaxf(mx0, __shfl_xor_sync(0xffffffffu, mx0, 1));
        mx0 = fmaxf(mx0, __shfl_xor_sync(0xffffffffu, mx0, 2));
        mx1 = fmaxf(mx1, __shfl_xor_sync(0xffffffffu, mx1, 1));
        mx1 = fmaxf(mx1, __shfl_xor_sync(0xffffffffu, mx1, 2));
        float mn0 = fmaxf(m0, mx0), mn1 = fmaxf(m1, mx1);
        float a0 = __expf(m0 - mn0), a1 = __expf(m1 - mn1);
        m0 = mn0; m1 = mn1;
        float s0 = 0.f, s1 = 0.f;
        #pragma unroll
        for (int t = 0; t < 8; t++) {
            sc[t][0] = __expf(sc[t][0] - mn0);
            sc[t][1] = __expf(sc[t][1] - mn0);
            sc[t][2] = __expf(sc[t][2] - mn1);
            sc[t][3] = __expf(sc[t][3] - mn1);
            s0 += sc[t][0] + sc[t][1];
            s1 += sc[t][2] + sc[t][3];
        }
        s0 += __shfl_xor_sync(0xffffffffu, s0, 1);
        s0 += __shfl_xor_sync(0xffffffffu, s0, 2);
        s1 += __shfl_xor_sync(0xffffffffu, s1, 1);
        s1 += __shfl_xor_sync(0xffffffffu, s1, 2);
        l0 = l0 * a0 + s0;
        l1 = l1 * a1 + s1;
        #pragma unroll
        for (int t = 0; t < 16; t++) {
            out[t][0] *= a0; out[t][1] *= a0;
            out[t][2] *= a1; out[t][3] *= a1;
        }

        // ---- O += P V ----
        #pragma unroll
        for (int ks = 0; ks < 4; ks++) {
            uint32_t pa[4];
            pa[0] = pack_h2(sc[2*ks][0],   sc[2*ks][1]);
            pa[1] = pack_h2(sc[2*ks][2],   sc[2*ks][3]);
            pa[2] = pack_h2(sc[2*ks+1][0], sc[2*ks+1][1]);
            pa[3] = pack_h2(sc[2*ks+1][2], sc[2*ks+1][3]);
            int j = 16 * ks + (lane & 15);
            #pragma unroll
            for (int dg = 0; dg < 8; dg++) {
                uint32_t voff = j * 256 + ((((dg << 1) | (lane >> 4)) ^ (j & 7)) << 4);
                uint32_t vb[2][2];
                LDSM4T(vb[0][0], vb[0][1], vb[1][0], vb[1][1], sV + voff);
                MMA16816F(out[2*dg],   pa, vb[0]);
                MMA16816F(out[2*dg+1], pa, vb[1]);
            }
        }
        cstage = (cstage == 2) ? 0 : cstage + 1;
        pstage = (pstage == 2) ? 0 : pstage + 1;
    }

    // ---- epilogue: single fp16 out ----
    float il0 = 1.f / l0, il1 = 1.f / l1;
    int r0g = tokQ + wq * 16 + (lane >> 2);
    size_t base0 = (size_t)r0g * DM + h * DHEAD + 2 * (lane & 3);
    size_t base1 = base0 + (size_t)8 * DM;
    #pragma unroll
    for (int t = 0; t < 16; t++) {
        *(__half2*)(Oh + base0 + t * 8) =
            __floats2half2_rn(out[t][0] * il0, out[t][1] * il0);
        *(__half2*)(Oh + base1 + t * 8) =
            __floats2half2_rn(out[t][2] * il1, out[t][3] * il1);
    }
}

// ---------------- launch ----------------
extern "C" void kernel_launch(void* const* d_in, const int* in_sizes, int n_in,
                              void* d_out, int out_size)
{
    const float* x   = (const float*)d_in[0];
    const float* Wq  = (const float*)d_in[1];
    const float* Wk  = (const float*)d_in[2];
    const float* Wv  = (const float*)d_in[3];
    const float* Wo  = (const float*)d_in[4];
    const float* kvc = (const float*)d_in[5];
    const int*   bt  = (const int*)d_in[7];
    float* out = (float*)d_out;
    float* cache_out = out + (size_t)T_TOK * DM;

    float *qp, *kp, *vp;
    __half *aoh, *hi, *lo, *wh, *khi, *vh;
    cudaGetSymbolAddress((void**)&qp,  g_q);
    cudaGetSymbolAddress((void**)&kp,  g_k);
    cudaGetSymbolAddress((void**)&vp,  g_v);
    cudaGetSymbolAddress((void**)&aoh, g_aoh);
    cudaGetSymbolAddress((void**)&hi,  g_hi);
    cudaGetSymbolAddress((void**)&lo,  g_lo);
    cudaGetSymbolAddress((void**)&wh,  g_wh);
    cudaGetSymbolAddress((void**)&khi, g_khi);
    cudaGetSymbolAddress((void**)&vh,  g_vh);

    cudaFuncSetAttribute(gemm_fp16, cudaFuncAttributeMaxDynamicSharedMemorySize, GEMM_SMEM);
    cudaFuncSetAttribute(flash_attn_hmma, cudaFuncAttributeMaxDynamicSharedMemorySize, FAH_SMEM);

    const int nx4 = T_TOK * DM / 4;
    const int nw4 = DM * DM / 4;
    const size_t wstride = (size_t)DM * DM;

    rope_table_kernel<<<SEQ * 64 / 256, 256>>>();

    // x single fp16 (1-term QKV GEMM)
    conv_fp16_kernel<<<nx4 / 256, 256>>>(x, hi, nx4);
    conv_fp16_kernel<<<nw4 / 256, 256>>>(Wq, wh,               nw4);
    conv_fp16_kernel<<<nw4 / 256, 256>>>(Wk, wh + wstride,     nw4);
    conv_fp16_kernel<<<nw4 / 256, 256>>>(Wv, wh + 2 * wstride, nw4);

    // fused QKV GEMM (1-term): grid.x = 48
    gemm_fp16<<<dim3(48, T_TOK / 128), 256, GEMM_SMEM>>>(
        hi, nullptr, wh, qp, kp, vp, 1, 0);

    // blocks 0..31 fully overwritten by scatter; copy only blocks 32..63
    {
        const size_t half_elems = (size_t)32 * 2 * NH * 256 * DHEAD;
        cudaMemcpyAsync(cache_out + half_elems, kvc + half_elems,
                        half_elems * sizeof(float), cudaMemcpyDeviceToDevice);
    }

    // rope + scatter + fp16 prep (q hi/lo overwrite x buffer; k single fp16)
    rope_scatter_prep<<<T_TOK, 256>>>(qp, kp, vp, bt, cache_out,
                                      hi, lo, khi, vh);

    flash_attn_hmma<<<dim3(SEQ / 128, NH, NSEQ), 256, FAH_SMEM>>>(
        hi, lo, khi, vh, aoh);

    conv_fp16_kernel<<<nw4 / 256, 256>>>(Wo, wh, nw4);
    // Wo GEMM (1-term): A = attention out single fp16
    gemm_fp16<<<dim3(16, T_TOK / 128), 256, GEMM_SMEM>>>(
        aoh, nullptr, wh, out, nullptr, nullptr, 0, 0);
}

// round 16
// speedup vs baseline: 1.6416x; 1.0704x over previous
#include <cuda_runtime.h>
#include <cuda_bf16.h>
#include <cuda_fp16.h>
#include <math.h>
#include <stdint.h>

#define T_TOK 8192
#define DM    2048
#define NH    16
#define DHEAD 128
#define SEQ   1024
#define NSEQ  8
#define GK    2048
#define QSCALE 0.08838834764831845f

// ---------------- scratch (static __device__, allocation-free) ----------------
__device__ float g_q[(size_t)T_TOK * DM];
__device__ float g_k[(size_t)T_TOK * DM];
__device__ float g_v[(size_t)T_TOK * DM];
__device__ __half g_aoh[(size_t)T_TOK * DM];     // attention out, single fp16
__device__ float g_cos[SEQ * 64];
__device__ float g_sin[SEQ * 64];
__device__ __half g_hi[(size_t)T_TOK * DM];      // x (single fp16), then q (single fp16)
__device__ __half g_wh[(size_t)4 * DM * DM];     // fp16 weights Wq|Wk|Wv|Wo
__device__ __half g_khi[(size_t)T_TOK * DM];
__device__ __half g_vh[(size_t)T_TOK * DM];

// ---------------- helpers ----------------
__device__ __forceinline__ uint32_t smem_u32(const void* p) {
    uint32_t a;
    asm("{ .reg .u64 t; cvta.to.shared.u64 t, %1; cvt.u32.u64 %0, t; }" : "=r"(a) : "l"(p));
    return a;
}
template<int N> __device__ __forceinline__ void cp_wait() {
    asm volatile("cp.async.wait_group %0;" :: "n"(N) : "memory");
}
__device__ __forceinline__ void cp_commit() {
    asm volatile("cp.async.commit_group;" ::: "memory");
}
__device__ __forceinline__ void cp_async16(uint32_t saddr, const void* gaddr) {
    asm volatile("cp.async.cg.shared.global [%0], [%1], 16;" :: "r"(saddr), "l"(gaddr));
}
#define LDSM4(r0, r1, r2, r3, addr) \
    asm volatile("ldmatrix.sync.aligned.m8n8.x4.shared.b16 {%0,%1,%2,%3}, [%4];" \
        : "=r"(r0), "=r"(r1), "=r"(r2), "=r"(r3) : "r"(addr))
#define LDSM4T(r0, r1, r2, r3, addr) \
    asm volatile("ldmatrix.sync.aligned.m8n8.x4.trans.shared.b16 {%0,%1,%2,%3}, [%4];" \
        : "=r"(r0), "=r"(r1), "=r"(r2), "=r"(r3) : "r"(addr))
#define MMA16816F(d, a, b) \
    asm volatile("mma.sync.aligned.m16n8k16.row.col.f32.f16.f16.f32 " \
        "{%0,%1,%2,%3}, {%4,%5,%6,%7}, {%8,%9}, {%0,%1,%2,%3};" \
        : "+f"((d)[0]), "+f"((d)[1]), "+f"((d)[2]), "+f"((d)[3]) \
        : "r"((a)[0]), "r"((a)[1]), "r"((a)[2]), "r"((a)[3]), "r"((b)[0]), "r"((b)[1]))

__device__ __forceinline__ uint32_t pack_h2(float a, float b) {
    __half2 h = __floats2half2_rn(a, b);
    return *reinterpret_cast<uint32_t*>(&h);
}

// ---------------- fused fp16 conversion: x + Wq + Wk + Wv + Wo ----------------
// granule layout: [0, 4M) = x, then 4 x 1M granules for the weights.
#define NX4 (T_TOK * DM / 4)          // 4194304
#define NW4 (DM * DM / 4)             // 1048576

__global__ __launch_bounds__(256) void conv_all_kernel(
    const float* __restrict__ x,
    const float* __restrict__ wq, const float* __restrict__ wk,
    const float* __restrict__ wv, const float* __restrict__ wo,
    __half* __restrict__ xh, __half* __restrict__ wh)
{
    int i = blockIdx.x * blockDim.x + threadIdx.x;
    const float* src;
    __half* dst;
    int j;
    if (i < NX4) {
        src = x; dst = xh; j = i;
    } else {
        int k = i - NX4;
        int seg = k >> 20;           // NW4 = 2^20
        j = k & (NW4 - 1);
        src = (seg == 0) ? wq : (seg == 1) ? wk : (seg == 2) ? wv : wo;
        dst = wh + (size_t)seg * DM * DM;
    }
    float4 v = ((const float4*)src)[j];
    ((__half2*)dst)[2*j]   = __floats2half2_rn(v.x, v.y);
    ((__half2*)dst)[2*j+1] = __floats2half2_rn(v.z, v.w);
}

// ---------------- RoPE cos/sin table ----------------
__global__ void rope_table_kernel() {
    int i = blockIdx.x * blockDim.x + threadIdx.x;
    int pos = i >> 6, j = i & 63;
    float inv = exp2f(-(float)j * 0.2076205059304593f);
    float ang = (float)pos * inv;
    float s, c;
    sincosf(ang, &s, &c);
    g_cos[i] = c;
    g_sin[i] = s;
}

// ------- HMMA fp16 GEMM: 256 thr, warp tile 64x32, 1-term -------
#define BK 64
#define NCHUNK (GK / BK)
#define TILE_B 16384
#define STAGE_B (2 * TILE_B)      // A | B
#define GEMM_SMEM (3 * STAGE_B)   // 98304

__global__ __launch_bounds__(256, 1) void gemm_fp16(
    const __half* __restrict__ A, const __half* __restrict__ B,
    float* __restrict__ C0, float* __restrict__ C1, float* __restrict__ C2,
    int three)
{
    extern __shared__ __align__(1024) char smraw[];
    const uint32_t smb = smem_u32(smraw);
    const int tid = threadIdx.x;
    const int lane = tid & 31, wid = tid >> 5;
    const int wm = wid >> 2, wn = wid & 3;            // warp grid 2(M) x 4(N)
    const int bx = blockIdx.x;
    const int brow = bx * 128;                        // row into weight buffer
    const int bm = blockIdx.y * 128;
    const int col = (bx & 15) * 128;                  // output column
    float* Cd = three ? ((bx >> 4) == 0 ? C0 : ((bx >> 4) == 1 ? C1 : C2)) : C0;

    const __half* srcs[2] = { A + (size_t)bm * GK, B + (size_t)brow * GK };

    float acc[4][4][4];
    #pragma unroll
    for (int mt = 0; mt < 4; mt++)
        #pragma unroll
        for (int nt = 0; nt < 4; nt++)
            #pragma unroll
            for (int j = 0; j < 4; j++) acc[mt][nt][j] = 0.f;

    auto prefetch = [&](int chunk_idx, int stg) {
        const uint32_t stb = smb + stg * STAGE_B;
        const int k0 = chunk_idx * BK;
        #pragma unroll
        for (int tile = 0; tile < 2; tile++) {
            const __half* g = srcs[tile] + k0;
            const uint32_t sbase = stb + tile * TILE_B;
            #pragma unroll
            for (int i = 0; i < 4; i++) {
                int idx = tid + 256 * i;
                int r = idx >> 3, c = idx & 7;
                uint32_t so = sbase + r * 128 + ((c ^ (r & 7)) << 4);
                cp_async16(so, g + (size_t)r * GK + c * 8);
            }
        }
    };

    prefetch(0, 0); cp_commit();
    prefetch(1, 1); cp_commit();

    int cstage = 0, pstage = 2;
    for (int i = 0; i < NCHUNK; i++) {
        if (i + 1 < NCHUNK) cp_wait<1>(); else cp_wait<0>();
        __syncthreads();
        if (i + 2 < NCHUNK) { prefetch(i + 2, pstage); cp_commit(); }

        const uint32_t stb = smb + cstage * STAGE_B;
        #pragma unroll
        for (int ks = 0; ks < 4; ks++) {
            uint32_t af[4][4];
            uint32_t bf[4][2];
            #pragma unroll
            for (int mt = 0; mt < 4; mt++) {
                int row = wm * 64 + mt * 16 + (lane & 15);
                uint32_t ad = stb + row * 128 + ((((ks << 1) | (lane >> 4)) ^ (row & 7)) << 4);
                LDSM4(af[mt][0], af[mt][1], af[mt][2], af[mt][3], ad);
            }
            #pragma unroll
            for (int nt2 = 0; nt2 < 2; nt2++) {
                int n = wn * 32 + nt2 * 16 + ((lane >> 4) << 3) + (lane & 7);
                uint32_t bd = stb + TILE_B + n * 128
                            + ((((ks << 1) | ((lane >> 3) & 1)) ^ (n & 7)) << 4);
                LDSM4(bf[nt2*2][0], bf[nt2*2][1], bf[nt2*2+1][0], bf[nt2*2+1][1], bd);
            }
            #pragma unroll
            for (int mt = 0; mt < 4; mt++)
                #pragma unroll
                for (int nt = 0; nt < 4; nt++)
                    MMA16816F(acc[mt][nt], af[mt], bf[nt]);
        }
        cstage = (cstage == 2) ? 0 : cstage + 1;
        pstage = (pstage == 2) ? 0 : pstage + 1;
    }

    #pragma unroll
    for (int mt = 0; mt < 4; mt++) {
        int r0 = bm + wm * 64 + mt * 16 + (lane >> 2);
        #pragma unroll
        for (int nt = 0; nt < 4; nt++) {
            int c0 = col + wn * 32 + nt * 8 + ((lane & 3) << 1);
            float* cp = Cd + (size_t)r0 * DM + c0;
            *(float2*)cp = make_float2(acc[mt][nt][0], acc[mt][nt][1]);
            *(float2*)(cp + (size_t)8 * DM) = make_float2(acc[mt][nt][2], acc[mt][nt][3]);
        }
    }
}

// ------ fused RoPE + paged KV scatter + fp16 attention prep (q scaled) ------
__global__ __launch_bounds__(256) void rope_scatter_prep(
    const float* __restrict__ q, const float* __restrict__ k,
    const float* __restrict__ v, const int* __restrict__ btab,
    float* __restrict__ cache,
    __half* __restrict__ qh, __half* __restrict__ khi, __half* __restrict__ vh)
{
    const int t   = blockIdx.x;
    const int pos = t & (SEQ - 1);
    const int seq = t >> 10;
    const int phys = btab[seq * 4 + (pos >> 8)];
    const int off  = pos & 255;
    const size_t tb = (size_t)t * DM;

    #pragma unroll
    for (int p = threadIdx.x; p < NH * 64; p += 256) {
        int h = p >> 6, j = p & 63;
        float c = g_cos[pos * 64 + j];
        float s = g_sin[pos * 64 + j];
        size_t base = tb + h * 128 + j;

        float q0 = q[base], q1 = q[base + 64];
        float nq0 = (q0 * c - q1 * s) * QSCALE;
        float nq1 = (q1 * c + q0 * s) * QSCALE;
        qh[base]      = __float2half_rn(nq0);
        qh[base + 64] = __float2half_rn(nq1);

        float k0 = k[base], k1 = k[base + 64];
        float nk0 = k0 * c - k1 * s;
        float nk1 = k1 * c + k0 * s;
        khi[base]      = __float2half_rn(nk0);
        khi[base + 64] = __float2half_rn(nk1);

        size_t cb = ((size_t)(phys * 32 + h) * 256 + off) * 128 + j;
        cache[cb]      = nk0;
        cache[cb + 64] = nk1;
    }
    #pragma unroll
    for (int e = threadIdx.x; e < DM; e += 256) {
        int h = e >> 7, d = e & 127;
        float vv = v[tb + e];
        size_t cb = ((size_t)(phys * 32 + 16 + h) * 256 + off) * 128 + d;
        cache[cb] = vv;
        vh[tb + e] = __float2half_rn(vv);
    }
}

// ---------------- flash attention, HMMA fp16 (1-term QK), 3-stage ----------------
// Q: 32KB at smb; stages at smb+32768 + st*32768: Kh 16K | V 16K
#define FAH_SMEM 131072

__global__ __launch_bounds__(256, 1) void flash_attn_hmma(
    const __half* __restrict__ Qhg, const __half* __restrict__ Khg,
    const __half* __restrict__ Vhg, __half* __restrict__ Oh)
{
    extern __shared__ __align__(1024) char sm[];
    const uint32_t smb = smem_u32(sm);
    const uint32_t sQh = smb;
    const int tid = threadIdx.x, lane = tid & 31, wq = tid >> 5;
    const int qt = (int)(gridDim.x - 1 - blockIdx.x);   // heavy tiles first
    const int h = blockIdx.y, b = blockIdx.z;
    const int tokQ = b * SEQ + qt * 128;
    const int nkt = 2 * qt + 2;

    auto load_kv = [&](int kt, int stg) {
        uint32_t st = smb + 32768 + stg * 32768;
        const __half* gh = Khg + (size_t)(b * SEQ + kt * 64) * DM + h * DHEAD;
        const __half* gv = Vhg + (size_t)(b * SEQ + kt * 64) * DM + h * DHEAD;
        #pragma unroll
        for (int i = 0; i < 4; i++) {
            int idx = tid + 256 * i;
            int r = idx >> 4, c = idx & 15;
            uint32_t off = r * 256 + ((c ^ (r & 7)) << 4);
            cp_async16(st + off, gh + (size_t)r * DM + c * 8);
            cp_async16(st + 16384 + off, gv + (size_t)r * DM + c * 8);
        }
    };

    {
        const __half* gq = Qhg + (size_t)tokQ * DM + h * DHEAD;
        #pragma unroll
        for (int i = 0; i < 8; i++) {
            int idx = tid + 256 * i;
            int r = idx >> 4, c = idx & 15;
            uint32_t off = r * 256 + ((c ^ (r & 7)) << 4);
            cp_async16(sQh + off, gq + (size_t)r * DM + c * 8);
        }
    }
    load_kv(0, 0); cp_commit();
    load_kv(1, 1); cp_commit();

    float m0 = -1e30f, m1 = -1e30f, l0 = 0.f, l1 = 0.f;
    float out[16][4];
    #pragma unroll
    for (int t = 0; t < 16; t++)
        #pragma unroll
        for (int j = 0; j < 4; j++) out[t][j] = 0.f;

    int cstage = 0, pstage = 2;
    for (int kt = 0; kt < nkt; kt++) {
        if (kt + 1 < nkt) cp_wait<1>(); else cp_wait<0>();
        __syncthreads();
        if (kt + 2 < nkt) { load_kv(kt + 2, pstage); cp_commit(); }

        const uint32_t sK = smb + 32768 + cstage * 32768;
        const uint32_t sV = sK + 16384;

        // ---- S = Q K^T (single-term fp16) ----
        float sc[8][4];
        #pragma unroll
        for (int t = 0; t < 8; t++)
            #pragma unroll
            for (int j = 0; j < 4; j++) sc[t][j] = 0.f;

        #pragma unroll
        for (int ks = 0; ks < 8; ks++) {
            uint32_t ah[4];
            int row = wq * 16 + (lane & 15);
            uint32_t aoff = row * 256 + ((((ks << 1) | (lane >> 4)) ^ (row & 7)) << 4);
            LDSM4(ah[0], ah[1], ah[2], ah[3], sQh + aoff);
            uint32_t bh[4][2][2];
            #pragma unroll
            for (int g = 0; g < 4; g++) {
                int n = g * 16 + ((lane >> 4) << 3) + (lane & 7);
                uint32_t boff = n * 256 + ((((ks << 1) | ((lane >> 3) & 1)) ^ (n & 7)) << 4);
                LDSM4(bh[g][0][0], bh[g][0][1], bh[g][1][0], bh[g][1][1], sK + boff);
            }
            #pragma unroll
            for (int g = 0; g < 4; g++) {
                MMA16816F(sc[2*g],   ah, bh[g][0]);
                MMA16816F(sc[2*g+1], ah, bh[g][1]);
            }
        }

        // ---- causal mask (scale pre-folded into q) ----
        const int qrow0 = qt * 128 + wq * 16 + (lane >> 2);
        if (kt >= 2 * qt) {
            const int kcol0 = kt * 64 + 2 * (lane & 3);
            #pragma unroll
            for (int t = 0; t < 8; t++) {
                int c = kcol0 + 8 * t;
                if (c     > qrow0    ) sc[t][0] = -1e30f;
                if (c + 1 > qrow0    ) sc[t][1] = -1e30f;
                if (c     > qrow0 + 8) sc[t][2] = -1e30f;
                if (c + 1 > qrow0 + 8) sc[t][3] = -1e30f;
            }
        }

        // ---- online softmax ----
        float mx0 = -1e30f, mx1 = -1e30f;
        #pragma unroll
        for (int t = 0; t < 8; t++) {
            mx0 = fmaxf(mx0, fmaxf(sc[t][0], sc[t][1]));
            mx1 = fmaxf(mx1, fmaxf(sc[t][2], sc[t][3]));
        }
        mx0 = fmaxf(mx0, __shfl_xor_sync(0xffffffffu, mx0, 1));
        mx0 = fmaxf(mx0, __shfl_xor_sync(0xffffffffu, mx0, 2));
        mx1 = fmaxf(mx1, __shfl_xor_sync(0xffffffffu, mx1, 1));
        mx1 = fmaxf(mx1, __shfl_xor_sync(0xffffffffu, mx1, 2));
        float mn0 = fmaxf(m0, mx0), mn1 = fmaxf(m1, mx1);
        float a0 = __expf(m0 - mn0), a1 = __expf(m1 - mn1);
        m0 = mn0; m1 = mn1;
        float s0 = 0.f, s1 = 0.f;
        #pragma unroll
        for (int t = 0; t < 8; t++) {
            sc[t][0] = __expf(sc[t][0] - mn0);
            sc[t][1] = __expf(sc[t][1] - mn0);
            sc[t][2] = __expf(sc[t][2] - mn1);
            sc[t][3] = __expf(sc[t][3] - mn1);
            s0 += sc[t][0] + sc[t][1];
            s1 += sc[t][2] + sc[t][3];
        }
        s0 += __shfl_xor_sync(0xffffffffu, s0, 1);
        s0 += __shfl_xor_sync(0xffffffffu, s0, 2);
        s1 += __shfl_xor_sync(0xffffffffu, s1, 1);
        s1 += __shfl_xor_sync(0xffffffffu, s1, 2);
        l0 = l0 * a0 + s0;
        l1 = l1 * a1 + s1;
        #pragma unroll
        for (int t = 0; t < 16; t++) {
            out[t][0] *= a0; out[t][1] *= a0;
            out[t][2] *= a1; out[t][3] *= a1;
        }

        // ---- O += P V ----
        #pragma unroll
        for (int ks = 0; ks < 4; ks++) {
            uint32_t pa[4];
            pa[0] = pack_h2(sc[2*ks][0],   sc[2*ks][1]);
            pa[1] = pack_h2(sc[2*ks][2],   sc[2*ks][3]);
            pa[2] = pack_h2(sc[2*ks+1][0], sc[2*ks+1][1]);
            pa[3] = pack_h2(sc[2*ks+1][2], sc[2*ks+1][3]);
            int j = 16 * ks + (lane & 15);
            #pragma unroll
            for (int dg = 0; dg < 8; dg++) {
                uint32_t voff = j * 256 + ((((dg << 1) | (lane >> 4)) ^ (j & 7)) << 4);
                uint32_t vb[2][2];
                LDSM4T(vb[0][0], vb[0][1], vb[1][0], vb[1][1], sV + voff);
                MMA16816F(out[2*dg],   pa, vb[0]);
                MMA16816F(out[2*dg+1], pa, vb[1]);
            }
        }
        cstage = (cstage == 2) ? 0 : cstage + 1;
        pstage = (pstage == 2) ? 0 : pstage + 1;
    }

    // ---- epilogue: single fp16 out ----
    float il0 = 1.f / l0, il1 = 1.f / l1;
    int r0g = tokQ + wq * 16 + (lane >> 2);
    size_t base0 = (size_t)r0g * DM + h * DHEAD + 2 * (lane & 3);
    size_t base1 = base0 + (size_t)8 * DM;
    #pragma unroll
    for (int t = 0; t < 16; t++) {
        *(__half2*)(Oh + base0 + t * 8) =
            __floats2half2_rn(out[t][0] * il0, out[t][1] * il0);
        *(__half2*)(Oh + base1 + t * 8) =
            __floats2half2_rn(out[t][2] * il1, out[t][3] * il1);
    }
}

// ---------------- launch ----------------
extern "C" void kernel_launch(void* const* d_in, const int* in_sizes, int n_in,
                              void* d_out, int out_size)
{
    const float* x   = (const float*)d_in[0];
    const float* Wq  = (const float*)d_in[1];
    const float* Wk  = (const float*)d_in[2];
    const float* Wv  = (const float*)d_in[3];
    const float* Wo  = (const float*)d_in[4];
    const float* kvc = (const float*)d_in[5];
    const int*   bt  = (const int*)d_in[7];
    float* out = (float*)d_out;
    float* cache_out = out + (size_t)T_TOK * DM;

    float *qp, *kp, *vp;
    __half *aoh, *hi, *wh, *khi, *vh;
    cudaGetSymbolAddress((void**)&qp,  g_q);
    cudaGetSymbolAddress((void**)&kp,  g_k);
    cudaGetSymbolAddress((void**)&vp,  g_v);
    cudaGetSymbolAddress((void**)&aoh, g_aoh);
    cudaGetSymbolAddress((void**)&hi,  g_hi);
    cudaGetSymbolAddress((void**)&wh,  g_wh);
    cudaGetSymbolAddress((void**)&khi, g_khi);
    cudaGetSymbolAddress((void**)&vh,  g_vh);

    cudaFuncSetAttribute(gemm_fp16, cudaFuncAttributeMaxDynamicSharedMemorySize, GEMM_SMEM);
    cudaFuncSetAttribute(flash_attn_hmma, cudaFuncAttributeMaxDynamicSharedMemorySize, FAH_SMEM);

    const size_t wstride = (size_t)DM * DM;

    rope_table_kernel<<<SEQ * 64 / 256, 256>>>();

    // single fused conversion: x + Wq + Wk + Wv + Wo
    conv_all_kernel<<<(NX4 + 4 * NW4) / 256, 256>>>(x, Wq, Wk, Wv, Wo, hi, wh);

    // fused QKV GEMM (1-term): grid.x = 48
    gemm_fp16<<<dim3(48, T_TOK / 128), 256, GEMM_SMEM>>>(
        hi, wh, qp, kp, vp, 1);

    // blocks 0..31 fully overwritten by scatter; copy only blocks 32..63
    {
        const size_t half_elems = (size_t)32 * 2 * NH * 256 * DHEAD;
        cudaMemcpyAsync(cache_out + half_elems, kvc + half_elems,
                        half_elems * sizeof(float), cudaMemcpyDeviceToDevice);
    }

    // rope + scatter + fp16 prep (q single fp16, reuses x buffer; k single fp16)
    rope_scatter_prep<<<T_TOK, 256>>>(qp, kp, vp, bt, cache_out,
                                      hi, khi, vh);

    flash_attn_hmma<<<dim3(SEQ / 128, NH, NSEQ), 256, FAH_SMEM>>>(
        hi, khi, vh, aoh);

    // Wo GEMM (1-term)
    gemm_fp16<<<dim3(16, T_TOK / 128), 256, GEMM_SMEM>>>(
        aoh, wh + 3 * wstride, out, nullptr, nullptr, 0);
}